// round 9
// baseline (speedup 1.0000x reference)
#include <cuda_runtime.h>
#include <math.h>

#define BB 2
#define SS 4096
#define DM 768
#define HH 12
#define OUTN 512
#define GRID 128
#define NTHR 512
#define ROWS_PB 64           // rows per block in stage 2
#define STROWS 16            // rows per subtile
#define NST 4                // subtiles per block
#define XSTR 772             // xbuf row stride (floats, 16B-multiple)
#define XBUFF 12352          // STROWS*XSTR
#define SCRP 17              // scr pad (conflict-free column)

// smem float offsets
#define OFF_U    0           // u_s: [m][h] 9216
#define OFF_X    9216        // 3 x-buffers, 12352 each
#define OFF_SCR  46272       // 192*17 = 3264
#define OFF_E    49536       // 192
#define SMEM_FLOATS 49728    // 198912 B

// ---------------- scratch ---------------------------------------------------
__device__ float g_qg[BB*DM];
__device__ float g_u[BB*DM*HH];          // [b][m][h]
__device__ float g_denom[BB*HH];
__device__ float g_y[GRID*HH*DM];        // per-block partial y [slot][h][m]
__device__ float g_og[BB*DM];            // init bvg, atomic accum
__device__ float g_part1[BB*DM];         // init bo,  atomic accum
__device__ float g_part2[BB*DM];         // init bp,  atomic accum
__device__ unsigned g_cnt;               // monotonic grid-barrier counter

// ---------------- f32x2 helpers ---------------------------------------------
#define FMA2(d,a,b,c) asm("fma.rn.f32x2 %0, %1, %2, %3;" : "=l"(d) : "l"(a), "l"(b), "l"(c))
#define ADD2(d,a,b)   asm("add.rn.f32x2 %0, %1, %2;" : "=l"(d) : "l"(a), "l"(b))
#define PACK2(d,lo,hi) asm("mov.b64 %0, {%1,%2};" : "=l"(d) : "f"(lo), "f"(hi))
#define UNPK2(lo,hi,s) asm("mov.b64 {%0,%1}, %2;" : "=f"(lo), "=f"(hi) : "l"(s))

// ---------------- grid barrier (monotonic counter; replay-safe) -------------
__device__ __forceinline__ void gbar() {
    __syncthreads();
    if (threadIdx.x == 0) {
        __threadfence();
        unsigned arr = atomicAdd(&g_cnt, 1u);
        unsigned target = (arr / GRID + 1u) * GRID;
        while (*((volatile unsigned*)&g_cnt) < target) __nanosleep(32);
        __threadfence();
    }
    __syncthreads();
}

__global__ __launch_bounds__(NTHR, 1)
void k_mega(const float* __restrict__ x,   const float* __restrict__ wqg,
            const float* __restrict__ bqg, const float* __restrict__ wkg,
            const float* __restrict__ wvg, const float* __restrict__ bvg,
            const float* __restrict__ wo,  const float* __restrict__ bo,
            const float* __restrict__ wp,  const float* __restrict__ bp,
            const float* __restrict__ wfc, const float* __restrict__ bfc,
            float* __restrict__ out) {
    extern __shared__ __align__(16) float sm[];
    const int blk = blockIdx.x;
    const int t = threadIdx.x;

    // ======== Stage 0: accumulator inits + qg (blocks 0..23) ================
    {
        int j = blk*NTHR + t;
        if (j < 1536)       g_og[j]         = bvg[j % DM];
        else if (j < 3072)  g_part1[j-1536] = bo[(j-1536) % DM];
        else if (j < 4608)  g_part2[j-3072] = bp[(j-3072) % DM];
        else if (j < 5632)  out[j-4608]     = bfc[(j-4608) % OUTN];
        else if (j < 5656)  g_denom[j-5632] = 0.f;
    }
    if (blk < 24) {
        int b = blk / 12, h = blk % 12;
        float* x0s = sm; float* redA = sm + 768;
        for (int i = t; i < DM; i += NTHR) x0s[i] = x[(size_t)b*SS*DM + i];
        __syncthreads();
        int o = t & 63, part = t >> 6;                 // 8 parts of 96 m
        float acc = 0.f;
        const float* wc = wqg + h*64 + o;
        #pragma unroll 16
        for (int j = 0; j < 96; j++) {
            int m = part*96 + j;
            acc += x0s[m] * wc[(size_t)m*DM];
        }
        redA[t] = acc;
        __syncthreads();
        if (t < 64) {
            float s = bqg[h*64 + t];
            #pragma unroll
            for (int k = 0; k < 8; k++) s += redA[k*64 + t];
            g_qg[b*DM + h*64 + t] = s * 0.125f;
        }
    }
    gbar();

    // ======== Stage 1: u[b,m,h] = qg[b,h,:]·wkg[m,h*64:] ====================
    {
        int b = blk >> 6, mc = blk & 63;     // 12 m's per block
        float* qgs = sm;
        for (int i = t; i < DM; i += NTHR) qgs[i] = g_qg[b*DM + i];
        __syncthreads();
        if (t < 144) {
            int mi = t / 12, h = t % 12;
            int m = mc*12 + mi;
            const float* w = wkg + (size_t)m*DM + h*64;
            const float* q = qgs + h*64;
            float acc = 0.f;
            #pragma unroll
            for (int d = 0; d < 64; d++) acc += q[d] * w[d];
            g_u[((size_t)m + (size_t)b*DM)*HH + h] = acc;   // [b][m][h]
        }
    }
    gbar();

    // ======== Stage 2: cp.async-pipelined scores -> exp -> weighted sums ====
    {
        const int b = blk >> 6;
        const int row0 = (blk & 63) * ROWS_PB;
        float* u_s = sm + OFF_U;
        float* scr = sm + OFF_SCR;
        float* e_s = sm + OFF_E;

        // --- issue subtile copy st -> buffer st%3 (all threads, 6 x 16B each)
        auto issue = [&](int st) {
            const float* gsrc = x + ((size_t)b*SS + row0 + st*STROWS)*DM;
            float* buf = sm + OFF_X + (st % 3)*XBUFF;
            #pragma unroll
            for (int k = 0; k < 6; k++) {
                int idx4 = t + k*NTHR;              // 0..3071
                int row = idx4 / 192, c4 = idx4 % 192;
                unsigned smaddr = (unsigned)__cvta_generic_to_shared(
                    buf + row*XSTR + c4*4);
                const float4* g = (const float4*)(gsrc + (size_t)row*DM) + c4;
                asm volatile("cp.async.cg.shared.global [%0], [%1], 16;"
                             :: "r"(smaddr), "l"(g) : "memory");
            }
            asm volatile("cp.async.commit_group;" ::: "memory");
        };

        issue(0);
        issue(1);

        // load u into smem (overlaps with async copies)
        {
            const float4* src = (const float4*)(g_u + (size_t)b*DM*HH);
            float4* dst = (float4*)u_s;
            for (int i = t; i < DM*HH/4; i += NTHR) dst[i] = src[i];
        }

        const int hh = t >> 8, tc = t & 255;
        unsigned long long acc[3][3];
        #pragma unroll
        for (int c = 0; c < 3; c++)
            #pragma unroll
            for (int k = 0; k < 3; k++) acc[c][k] = 0ull;
        float dloc = 0.f;

        #pragma unroll
        for (int st = 0; st < NST; st++) {
            if (st + 2 < NST) issue(st + 2);
            if (st < 2)       asm volatile("cp.async.wait_group 2;" ::: "memory");
            else if (st == 2) asm volatile("cp.async.wait_group 1;" ::: "memory");
            else              asm volatile("cp.async.wait_group 0;" ::: "memory");
            __syncthreads();

            const float* xb = sm + OFF_X + (st % 3)*XBUFF;

            // ---- phase 1: warp-m-split scores. warp w owns m in [48w,48w+48)
            {
                int w = t >> 5, l = t & 31;
                int row = l >> 1, mh = l & 1;
                int m0 = w*48 + mh*24;
                const float4* xr = (const float4*)(xb + row*XSTR + m0);
                const float* up = u_s + m0*HH;
                unsigned long long a2[6];
                #pragma unroll
                for (int k = 0; k < 6; k++) a2[k] = 0ull;
                #pragma unroll
                for (int i = 0; i < 6; i++) {
                    float4 xv = xr[i];
                    #pragma unroll
                    for (int j = 0; j < 4; j++) {
                        float xs = (j==0) ? xv.x : (j==1) ? xv.y
                                 : (j==2) ? xv.z : xv.w;
                        unsigned long long xx;
                        PACK2(xx, xs, xs);
                        const ulonglong2* uu =
                            (const ulonglong2*)(up + (i*4 + j)*HH);
                        ulonglong2 u0 = uu[0], u1 = uu[1], u2 = uu[2];
                        FMA2(a2[0], xx, u0.x, a2[0]);
                        FMA2(a2[1], xx, u0.y, a2[1]);
                        FMA2(a2[2], xx, u1.x, a2[2]);
                        FMA2(a2[3], xx, u1.y, a2[3]);
                        FMA2(a2[4], xx, u2.x, a2[4]);
                        FMA2(a2[5], xx, u2.y, a2[5]);
                    }
                }
                // combine the two m-halves of each row (lane pair)
                #pragma unroll
                for (int k = 0; k < 6; k++) {
                    unsigned long long o2 =
                        __shfl_xor_sync(0xffffffffu, a2[k], 1);
                    ADD2(a2[k], a2[k], o2);
                }
                if (mh == 0) {
                    float v[12];
                    #pragma unroll
                    for (int k = 0; k < 6; k++) UNPK2(v[2*k], v[2*k+1], a2[k]);
                    #pragma unroll
                    for (int h = 0; h < 12; h++)
                        scr[(row*HH + h)*SCRP + w] = v[h];
                }
            }
            __syncthreads();

            // ---- cross-warp reduce + exp
            if (t < STROWS*HH) {
                float s = 0.f;
                #pragma unroll
                for (int w = 0; w < 16; w++) s += scr[t*SCRP + w];
                e_s[t] = __expf(s);
            }
            __syncthreads();

            // ---- denominator partial
            if (t < HH) {
                #pragma unroll
                for (int j = 0; j < STROWS; j++) dloc += e_s[j*HH + t];
            }

            // ---- phase 2: y[h][m] += sum_s e[s][h]*x[s][m]
            {
                #pragma unroll 4
                for (int s = 0; s < STROWS; s++) {
                    float xv0 = xb[s*XSTR + tc];
                    float xv1 = xb[s*XSTR + 256 + tc];
                    float xv2 = xb[s*XSTR + 512 + tc];
                    unsigned long long xx0, xx1, xx2;
                    PACK2(xx0, xv0, xv0);
                    PACK2(xx1, xv1, xv1);
                    PACK2(xx2, xv2, xv2);
                    const unsigned long long* ep =
                        (const unsigned long long*)(e_s + s*HH + hh*6);
                    unsigned long long e0 = ep[0], e1 = ep[1], e2 = ep[2];
                    FMA2(acc[0][0], e0, xx0, acc[0][0]);
                    FMA2(acc[0][1], e1, xx0, acc[0][1]);
                    FMA2(acc[0][2], e2, xx0, acc[0][2]);
                    FMA2(acc[1][0], e0, xx1, acc[1][0]);
                    FMA2(acc[1][1], e1, xx1, acc[1][1]);
                    FMA2(acc[1][2], e2, xx1, acc[1][2]);
                    FMA2(acc[2][0], e0, xx2, acc[2][0]);
                    FMA2(acc[2][1], e1, xx2, acc[2][1]);
                    FMA2(acc[2][2], e2, xx2, acc[2][2]);
                }
            }
            __syncthreads();   // buffer reuse fence before next issue
        }

        // ---- write this block's y slot (no atomics) + denom
        {
            size_t base = (size_t)blk*HH + hh*6;
            #pragma unroll
            for (int c = 0; c < 3; c++)
                #pragma unroll
                for (int k = 0; k < 3; k++) {
                    float f0, f1;
                    UNPK2(f0, f1, acc[c][k]);
                    g_y[(base + 2*k  )*DM + c*256 + tc] = f0;
                    g_y[(base + 2*k+1)*DM + c*256 + tc] = f1;
                }
        }
        if (t < HH) atomicAdd(&g_denom[b*HH + t], dloc);
    }
    gbar();

    // ======== Stage 3: og = (y/denom) @ wvg slice (96 blocks) ===============
    if (blk < 96) {
        int b = blk / 48; int r = blk % 48;
        int h = r >> 2; int sub = r & 3;                 // 4 subs of 192 m
        float* redR = sm;            // 384
        float* y_s  = sm + 384;      // 192
        float* redG = sm + 768;      // 512
        float inv = 1.f / __ldcg(&g_denom[b*HH + h]);
        if (t < 384) {
            int e = t % 192, prt = t / 192;              // 2 parts x 32 slots
            float s = 0.f;
            #pragma unroll 8
            for (int sl = b*64 + prt*32; sl < b*64 + prt*32 + 32; sl++)
                s += g_y[((size_t)sl*HH + h)*DM + sub*192 + e];
            redR[t] = s;
        }
        __syncthreads();
        if (t < 192) y_s[t] = (redR[t] + redR[192+t]) * inv;
        __syncthreads();
        int o = t & 63, q = t >> 6;          // 8 parts of 24 m
        float acc = 0.f;
        const float* wc = wvg + h*64 + o;
        #pragma unroll
        for (int j = 0; j < 24; j++) {
            int ml = q*24 + j;
            acc += y_s[ml] * wc[(size_t)(sub*192 + ml)*DM];
        }
        redG[t] = acc;
        __syncthreads();
        if (t < 64) {
            float s = 0.f;
            #pragma unroll
            for (int k = 0; k < 8; k++) s += redG[k*64 + t];
            atomicAdd(&g_og[b*DM + h*64 + t], s);
        }
    }
    gbar();

    // ======== Stage 4: attn0 partials: og @ wo (72 blocks) ==================
    if (blk < 72) {
        int b = blk / 36; int r = blk % 36;
        int oc = r / 12;  int mcp = r % 12;      // 64-m chunk
        float* in_s = sm;
        if (t < 64) in_s[t] = __ldcg(&g_og[b*DM + mcp*64 + t]);
        __syncthreads();
        int o = oc*256 + (t & 255), mh = t >> 8;
        float acc = 0.f;
        const float* wc = wo + o;
        #pragma unroll
        for (int j = 0; j < 32; j++)
            acc += in_s[mh*32 + j] * wc[(size_t)(mcp*64 + mh*32 + j)*DM];
        atomicAdd(&g_part1[b*DM + o], acc);
    }
    gbar();

    // ======== Stage 5: pre-tanh pooled partials: attn0 @ wp =================
    if (blk < 72) {
        int b = blk / 36; int r = blk % 36;
        int oc = r / 12;  int mcp = r % 12;
        float* in_s = sm;
        __syncthreads();
        if (t < 64) in_s[t] = __ldcg(&g_part1[b*DM + mcp*64 + t]);
        __syncthreads();
        int o = oc*256 + (t & 255), mh = t >> 8;
        float acc = 0.f;
        const float* wc = wp + o;
        #pragma unroll
        for (int j = 0; j < 32; j++)
            acc += in_s[mh*32 + j] * wc[(size_t)(mcp*64 + mh*32 + j)*DM];
        atomicAdd(&g_part2[b*DM + o], acc);
    }
    gbar();

    // ======== Stage 6: out += tanh(part2) @ wfc (48 blocks) =================
    if (blk < 48) {
        int b = blk / 24; int r = blk % 24;
        int oc = r / 12;  int mcp = r % 12;
        float* in_s = sm;
        if (t < 64) in_s[t] = tanhf(__ldcg(&g_part2[b*DM + mcp*64 + t]));
        __syncthreads();
        int o = oc*256 + (t & 255), mh = t >> 8;
        float acc = 0.f;
        const float* wc = wfc + o;
        #pragma unroll
        for (int j = 0; j < 32; j++)
            acc += in_s[mh*32 + j] * wc[(size_t)(mcp*64 + mh*32 + j)*OUTN];
        atomicAdd(&out[b*OUTN + o], acc);
    }
}

// ---------------- launch ----------------------------------------------------
extern "C" void kernel_launch(void* const* d_in, const int* in_sizes, int n_in,
                              void* d_out, int out_size) {
    const float* x   = (const float*)d_in[0];
    const float* wqg = (const float*)d_in[7];
    const float* bqg = (const float*)d_in[8];
    const float* wkg = (const float*)d_in[9];
    const float* wvg = (const float*)d_in[11];
    const float* bvg = (const float*)d_in[12];
    const float* wo  = (const float*)d_in[13];
    const float* bo  = (const float*)d_in[14];
    const float* wp  = (const float*)d_in[15];
    const float* bp  = (const float*)d_in[16];
    const float* wfc = (const float*)d_in[17];
    const float* bfc = (const float*)d_in[18];
    float* out = (float*)d_out;

    const size_t smem = (size_t)SMEM_FLOATS * sizeof(float); // 198912 B
    static int configured = 0;
    if (!configured) {
        cudaFuncSetAttribute(k_mega, cudaFuncAttributeMaxDynamicSharedMemorySize,
                             (int)smem);
        configured = 1;
    }
    k_mega<<<GRID, NTHR, smem>>>(x, wqg, bqg, wkg, wvg, bvg, wo, bo, wp, bp,
                                 wfc, bfc, out);
}